// round 6
// baseline (speedup 1.0000x reference)
#include <cuda_runtime.h>
#include <cstdint>
#include <math.h>

#define EPS_BN    1e-5f
#define FT_SMOOTH 1e-5f

#define CH   96
#define HW   128
#define NB   8
#define NPIX (NB*HW*HW)        /* 131072 */

// ======================= device scratch =======================
__device__ float g_q[(size_t)NPIX * CH];
__device__ float g_k[(size_t)NPIX * CH];
__device__ float g_v[(size_t)NPIX * CH];
__device__ float g_att_spat[NPIX];
__device__ float g_part[1024 * 96 * 3];
__device__ float g_att_chan[NB * CH];
// Fragment-order permuted tf32 weights: [3 convs][27 chunks][32 lanes][96 slots]
// slot = ks*24 + nb*2 + k4  ->  value B[k = ks*8 + tig + 4*k4][n = nb*8 + gid]
__device__ float g_Bw[3 * 27 * 32 * 96];

// ======================= math helpers =======================
__device__ __forceinline__ float ftanimoto(float tpl, float tpp, float tll) {
    float num = tpl + FT_SMOOTH;
    float s   = tpp + tll;
    float den = 0.f;
#pragma unroll
    for (int d = 0; d < 5; ++d) {
        float a = (float)(1 << d);
        float b = -(2.f * a - 1.f);
        den += 1.f / (a * s + b * tpl + FT_SMOOTH);
    }
    return num * den * 0.2f;
}
__device__ __forceinline__ float sigmoidf_(float x) { return 1.f / (1.f + expf(-x)); }
__device__ __forceinline__ float f2tf32f(float v) {
    uint32_t t; asm("cvt.rna.tf32.f32 %0, %1;" : "=r"(t) : "f"(v));
    return __uint_as_float(t);
}

// mma.sync m16n8k8 tf32 (HMMA path; sm_80+ PTX, valid on compute_103)
__device__ __forceinline__ void mma_tf32(float4& d, const float4 a, float b0, float b1) {
    asm volatile(
        "mma.sync.aligned.m16n8k8.row.col.f32.tf32.tf32.f32 "
        "{%0,%1,%2,%3}, {%4,%5,%6,%7}, {%8,%9}, {%0,%1,%2,%3};"
        : "+f"(d.x), "+f"(d.y), "+f"(d.z), "+f"(d.w)
        : "r"(__float_as_uint(a.x)), "r"(__float_as_uint(a.y)),
          "r"(__float_as_uint(a.z)), "r"(__float_as_uint(a.w)),
          "r"(__float_as_uint(b0)), "r"(__float_as_uint(b1)));
}

// ======================= weight prep (fragment-order permute) ===========
// 81 blocks (conv*27+chunk), 128 threads: thread t -> lane l = t>>2, ks = t&3
__global__ void prep_weights(const float* __restrict__ wq,
                             const float* __restrict__ wk,
                             const float* __restrict__ wv)
{
    int conv = blockIdx.x / 27;
    int c    = blockIdx.x % 27;
    const float* w = (conv == 0) ? wq : (conv == 1) ? wk : wv;
    int dy = c / 9, dx = (c % 9) / 3, ci0 = (c % 3) * 32;
    int t   = threadIdx.x;
    int l   = t >> 2;           // consumer lane 0..31
    int ks  = t & 3;
    int gid = l >> 2, tig = l & 3;
    float* dst = g_Bw + ((size_t)(conv * 27 + c) * 32 + l) * 96;
#pragma unroll
    for (int r = 0; r < 24; ++r) {
        int nb = r >> 1, k4 = r & 1;
        int k  = ks * 8 + tig + 4 * k4;
        int n  = nb * 8 + gid;
        float v = w[(((dy * 3 + dx) * CH) + ci0 + k) * CH + n];
        dst[ks * 24 + r] = f2tf32f(v);
    }
}

// ======================= conv via mma.sync TF32 =======================
// Block: 128 threads (4 warps). Tile: 64 pixels x 96 couts; warp = 16 px x 96.
// smem A: fragment-order [128 consumer lanes][20] (16 slots + pad), double-buffered.
//   slot(jc, jr) = 2*jc + jr -> value x[row = gid + 8*jr][col = tig + 4*jc]
//   => float4 at 4*ks = (a0,a1,a2,a3) of k-step ks.
// smem B: fragment-order [32 lanes][100] (96 slots + pad), double-buffered.
#define AP_STRIDE 20
#define BP_STRIDE 100

__global__ void __launch_bounds__(128)
conv_mma_kernel(const float* __restrict__ x1, const float* __restrict__ x2,
                const float* __restrict__ x3,
                const float* __restrict__ gq, const float* __restrict__ bq,
                const float* __restrict__ mq, const float* __restrict__ vq,
                const float* __restrict__ gk, const float* __restrict__ bk,
                const float* __restrict__ mk, const float* __restrict__ vk,
                const float* __restrict__ gv, const float* __restrict__ bv,
                const float* __restrict__ mv, const float* __restrict__ vvv)
{
    __shared__ __align__(16) float sAp[2][128 * AP_STRIDE];   // 2 x 10240 B
    __shared__ __align__(16) float sBp[2][32 * BP_STRIDE];    // 2 x 12800 B
    __shared__ float s_scale[CH], s_shift[CH];

    const int tid  = threadIdx.x;
    const int conv = blockIdx.y;
    const int tb   = blockIdx.x;            // 0..2047
    const int b    = tb >> 8;               // batch
    const int y    = (tb >> 1) & 127;       // output row
    const int x0   = (tb & 1) * 64;         // x tile base

    const float* xin = (conv == 0) ? x1 : (conv == 1) ? x2 : x3;
    float* outp      = (conv == 0) ? g_q : (conv == 1) ? g_k : g_v;

    if (tid < CH) {
        const float* gm = (conv == 0) ? gq : (conv == 1) ? gk : gv;
        const float* bt = (conv == 0) ? bq : (conv == 1) ? bk : bv;
        const float* mu = (conv == 0) ? mq : (conv == 1) ? mk : mv;
        const float* vr = (conv == 0) ? vq : (conv == 1) ? vk : vvv;
        float s = gm[tid] * rsqrtf(vr[tid] + EPS_BN);
        s_scale[tid] = s;
        s_shift[tid] = bt[tid] - mu[tid] * s;
    }

    const int lane = tid & 31;
    const int wp   = tid >> 5;
    const int gid  = lane >> 2;   // 0..7
    const int tig  = lane & 3;    // 0..3

    // B-copy staging role: 4 threads per lane row
    const int cl = tid >> 2;      // lane row 0..31
    const int cq = tid & 3;       // quarter 0..3

    const size_t imgbase = (size_t)b * (HW * HW * CH);
    const float* Bw = g_Bw + (size_t)conv * 27 * (32 * 96);

    float a_pre[16];   // A slot values for this thread's consumer row
    uint4 b_pre[6];    // B copy slice

    auto load_chunk = [&](int c) {
        const int dy  = c / 9;
        const int dxx = (c % 9) / 3;
        const int ci0 = (c % 3) * 32;
        const int gy  = y + dy - 1;
        // consumer row (wp, lane): rows gid + 8*jr of warp tile, cols tig + 4*jc
#pragma unroll
        for (int jr = 0; jr < 2; ++jr) {
            const int gx = x0 + wp * 16 + gid + 8 * jr + dxx - 1;
            if ((unsigned)gy < (unsigned)HW && (unsigned)gx < (unsigned)HW) {
                const float* src = xin + imgbase +
                                   ((size_t)(gy * HW + gx) * CH + ci0 + tig);
#pragma unroll
                for (int jc = 0; jc < 8; ++jc)
                    a_pre[2 * jc + jr] = src[4 * jc];
            } else {
#pragma unroll
                for (int jc = 0; jc < 8; ++jc)
                    a_pre[2 * jc + jr] = 0.f;
            }
        }
        const uint4* wsrc = (const uint4*)(Bw + ((size_t)c * 32 + cl) * 96 + cq * 24);
#pragma unroll
        for (int m = 0; m < 6; ++m) b_pre[m] = wsrc[m];
    };

    auto store_chunk = [&](int buf) {
        float* adst = sAp[buf] + tid * AP_STRIDE;
#pragma unroll
        for (int q = 0; q < 4; ++q) {
            float4 v;
            v.x = f2tf32f(a_pre[4 * q + 0]);
            v.y = f2tf32f(a_pre[4 * q + 1]);
            v.z = f2tf32f(a_pre[4 * q + 2]);
            v.w = f2tf32f(a_pre[4 * q + 3]);
            *(float4*)(adst + 4 * q) = v;
        }
        uint4* bdst = (uint4*)(sBp[buf] + cl * BP_STRIDE + cq * 24);
#pragma unroll
        for (int m = 0; m < 6; ++m) bdst[m] = b_pre[m];
    };

    float4 C[12];
#pragma unroll
    for (int i = 0; i < 12; ++i) C[i] = make_float4(0.f, 0.f, 0.f, 0.f);

    load_chunk(0);
    store_chunk(0);
    __syncthreads();

    for (int c = 0; c < 27; ++c) {
        const int cur = c & 1;
        if (c < 26) load_chunk(c + 1);

        const float* Ap = sAp[cur] + tid * AP_STRIDE;
        const float* Bp = sBp[cur] + lane * BP_STRIDE;
#pragma unroll
        for (int ks = 0; ks < 4; ++ks) {
            float4 af = *(const float4*)(Ap + 4 * ks);
            float4 bf[6];
#pragma unroll
            for (int m = 0; m < 6; ++m)
                bf[m] = *(const float4*)(Bp + ks * 24 + 4 * m);
#pragma unroll
            for (int m = 0; m < 6; ++m) {
                mma_tf32(C[2 * m],     af, bf[m].x, bf[m].y);
                mma_tf32(C[2 * m + 1], af, bf[m].z, bf[m].w);
            }
        }
        if (c < 26) {
            store_chunk((c + 1) & 1);
            __syncthreads();
        }
    }

    // ---- epilogue: BN + sigmoid, float2 stores (c0,c1 adjacent cols) ----
    const int px = x0 + wp * 16 + gid;
    float* orow0 = outp + imgbase + ((size_t)(y * HW) + px) * CH;
    float* orow1 = orow0 + 8 * CH;      // pixel px+8
#pragma unroll
    for (int nb = 0; nb < 12; ++nb) {
        int col = nb * 8 + 2 * tig;
        float sc0 = s_scale[col],     sh0 = s_shift[col];
        float sc1 = s_scale[col + 1], sh1 = s_shift[col + 1];
        float2 r0, r1;
        r0.x = sigmoidf_(C[nb].x * sc0 + sh0);
        r0.y = sigmoidf_(C[nb].y * sc1 + sh1);
        r1.x = sigmoidf_(C[nb].z * sc0 + sh0);
        r1.y = sigmoidf_(C[nb].w * sc1 + sh1);
        *(float2*)(orow0 + col) = r0;
        *(float2*)(orow1 + col) = r1;
    }
}

// ======================= attention + final =======================
__global__ __launch_bounds__(256)
void spat_att_kernel()
{
    int p    = blockIdx.x * 8 + (threadIdx.x >> 5);
    int lane = threadIdx.x & 31;
    const float* qp = g_q + (size_t)p * CH;
    const float* kp = g_k + (size_t)p * CH;
    float tpl = 0.f, tpp = 0.f, tll = 0.f;
#pragma unroll
    for (int i = 0; i < 3; ++i) {
        float a = qp[lane + i * 32];
        float b = kp[lane + i * 32];
        tpl += a * b; tpp += a * a; tll += b * b;
    }
#pragma unroll
    for (int off = 16; off; off >>= 1) {
        tpl += __shfl_xor_sync(0xffffffffu, tpl, off);
        tpp += __shfl_xor_sync(0xffffffffu, tpp, off);
        tll += __shfl_xor_sync(0xffffffffu, tll, off);
    }
    if (lane == 0) g_att_spat[p] = ftanimoto(tpl, tpp, tll);
}

// stage 1: 1024 blocks (b, 128-pixel slice), 192 threads (96 c x 2 halves)
__global__ __launch_bounds__(192)
void chan_part_kernel()
{
    __shared__ float sp[2][96][3];
    const int t    = threadIdx.x;
    const int c    = t % 96;
    const int half = t / 96;
    const int blk  = blockIdx.x;         // 0..1023
    const int b    = blk >> 7;
    const int sl   = blk & 127;
    const size_t pixbase = (size_t)b * 16384 + sl * 128 + half * 64;
    const float* qb = g_q + pixbase * CH + c;
    const float* kb = g_k + pixbase * CH + c;
    float tpl = 0.f, tpp = 0.f, tll = 0.f;
#pragma unroll 4
    for (int i = 0; i < 64; ++i) {
        size_t off = (size_t)i * CH;
        float a = qb[off];
        float bb = kb[off];
        tpl += a * bb; tpp += a * a; tll += bb * bb;
    }
    sp[half][c][0] = tpl; sp[half][c][1] = tpp; sp[half][c][2] = tll;
    __syncthreads();
    if (t < 96) {
        float* o = g_part + blk * 288 + t * 3;
        o[0] = sp[0][t][0] + sp[1][t][0];
        o[1] = sp[0][t][1] + sp[1][t][1];
        o[2] = sp[0][t][2] + sp[1][t][2];
    }
}

// stage 2: reduce 128 slices per (b,c)
__global__ void chan_att_kernel()
{
    int b = blockIdx.x;
    int c = threadIdx.x;    // 96 threads
    float tpl = 0.f, tpp = 0.f, tll = 0.f;
    for (int i = 0; i < 128; ++i) {
        const float* pp = g_part + ((size_t)(b * 128 + i)) * 288 + c * 3;
        tpl += pp[0]; tpp += pp[1]; tll += pp[2];
    }
    g_att_chan[b * CH + c] = ftanimoto(tpl, tpp, tll);
}

__global__ __launch_bounds__(256)
void final_kernel(const float* __restrict__ gn, const float* __restrict__ bnb,
                  const float* __restrict__ mn, const float* __restrict__ vn,
                  float* __restrict__ out)
{
    int i4   = blockIdx.x * 256 + threadIdx.x;
    int flat = i4 * 4;
    int pix  = flat / CH;
    int c    = flat % CH;
    int b    = pix >> 14;

    float4 v4 = *(const float4*)(g_v + (size_t)flat);
    float  as = g_att_spat[pix];
    float4 ac = *(const float4*)(g_att_chan + b * CH + c);
    float4 gg = *(const float4*)(gn  + c);
    float4 bb = *(const float4*)(bnb + c);
    float4 mm = *(const float4*)(mn  + c);
    float4 vv = *(const float4*)(vn  + c);

    float4 r;
    float s;
    s = gg.x * rsqrtf(vv.x + EPS_BN); r.x = (0.5f * v4.x * (ac.x + as) - mm.x) * s + bb.x;
    s = gg.y * rsqrtf(vv.y + EPS_BN); r.y = (0.5f * v4.y * (ac.y + as) - mm.y) * s + bb.y;
    s = gg.z * rsqrtf(vv.z + EPS_BN); r.z = (0.5f * v4.z * (ac.z + as) - mm.z) * s + bb.z;
    s = gg.w * rsqrtf(vv.w + EPS_BN); r.w = (0.5f * v4.w * (ac.w + as) - mm.w) * s + bb.w;
    *(float4*)(out + (size_t)flat) = r;
}

// ======================= launch =======================
extern "C" void kernel_launch(void* const* d_in, const int* in_sizes, int n_in,
                              void* d_out, int out_size)
{
    const float* x1 = (const float*)d_in[0];
    const float* x2 = (const float*)d_in[1];
    const float* x3 = (const float*)d_in[2];
    const float* wq = (const float*)d_in[3];
    const float* gq = (const float*)d_in[4];
    const float* bq = (const float*)d_in[5];
    const float* mq = (const float*)d_in[6];
    const float* vq = (const float*)d_in[7];
    const float* wk = (const float*)d_in[8];
    const float* gk = (const float*)d_in[9];
    const float* bk = (const float*)d_in[10];
    const float* mk = (const float*)d_in[11];
    const float* vk = (const float*)d_in[12];
    const float* wv = (const float*)d_in[13];
    const float* gv = (const float*)d_in[14];
    const float* bv = (const float*)d_in[15];
    const float* mv = (const float*)d_in[16];
    const float* vv = (const float*)d_in[17];
    const float* gn  = (const float*)d_in[18];
    const float* bnb = (const float*)d_in[19];
    const float* mn  = (const float*)d_in[20];
    const float* vn  = (const float*)d_in[21];

    prep_weights<<<81, 128>>>(wq, wk, wv);

    dim3 cgrid(2048, 3);   // (2 x-tiles * 128 rows * 8 batches) x 3 convs
    conv_mma_kernel<<<cgrid, 128>>>(x1, x2, x3,
                                    gq, bq, mq, vq,
                                    gk, bk, mk, vk,
                                    gv, bv, mv, vv);

    spat_att_kernel<<<NPIX / 8, 256>>>();
    chan_part_kernel<<<1024, 192>>>();
    chan_att_kernel<<<NB, 96>>>();
    final_kernel<<<(NPIX * CH / 4) / 256, 256>>>(gn, bnb, mn, vn, (float*)d_out);
}

// round 7
// speedup vs baseline: 1.9055x; 1.9055x over previous
#include <cuda_runtime.h>
#include <cstdint>
#include <math.h>

#define EPS_BN    1e-5f
#define FT_SMOOTH 1e-5f

#define CH   96
#define HW   128
#define NB   8
#define NPIX (NB*HW*HW)        /* 131072 */

// ======================= device scratch =======================
__device__ float g_q[(size_t)NPIX * CH];
__device__ float g_k[(size_t)NPIX * CH];
__device__ float g_v[(size_t)NPIX * CH];
__device__ float g_att_spat[NPIX];
__device__ float g_part[1024 * 96 * 3];
__device__ float g_att_chan[NB * CH];
// Pre-converted tf32 weights: [3 convs][27 chunks][32 k][96 cout]
__device__ float g_Bw[3 * 27 * 32 * 96];

// ======================= math helpers =======================
__device__ __forceinline__ float ftanimoto(float tpl, float tpp, float tll) {
    float num = tpl + FT_SMOOTH;
    float s   = tpp + tll;
    float den = 0.f;
#pragma unroll
    for (int d = 0; d < 5; ++d) {
        float a = (float)(1 << d);
        float b = -(2.f * a - 1.f);
        den += 1.f / (a * s + b * tpl + FT_SMOOTH);
    }
    return num * den * 0.2f;
}
__device__ __forceinline__ float sigmoidf_(float x) { return 1.f / (1.f + expf(-x)); }
__device__ __forceinline__ float f2tf32f(float v) {
    uint32_t t; asm("cvt.rna.tf32.f32 %0, %1;" : "=r"(t) : "f"(v));
    return __uint_as_float(t);
}

// mma.sync m16n8k8 tf32 (HMMA path; sm_80+ PTX, valid on compute_103)
__device__ __forceinline__ void mma_tf32(float4& d, const uint32_t a[4], const uint32_t b[2]) {
    asm volatile(
        "mma.sync.aligned.m16n8k8.row.col.f32.tf32.tf32.f32 "
        "{%0,%1,%2,%3}, {%4,%5,%6,%7}, {%8,%9}, {%0,%1,%2,%3};"
        : "+f"(d.x), "+f"(d.y), "+f"(d.z), "+f"(d.w)
        : "r"(a[0]), "r"(a[1]), "r"(a[2]), "r"(a[3]), "r"(b[0]), "r"(b[1]));
}

// ======================= weight prep (R5 layout) =======================
// block = (conv*27 + chunk), 96 threads (one per cout)
// g_Bw layout per chunk: [k=0..31][cout=0..95], tf32-rounded
__global__ void prep_weights(const float* __restrict__ wq,
                             const float* __restrict__ wk,
                             const float* __restrict__ wv)
{
    int conv = blockIdx.x / 27;
    int c    = blockIdx.x % 27;
    const float* w = (conv == 0) ? wq : (conv == 1) ? wk : wv;
    int dy = c / 9, dx = (c % 9) / 3, ci0 = (c % 3) * 32;
    int co = threadIdx.x;                       // 0..95
    float* dst = g_Bw + (size_t)(conv * 27 + c) * (32 * 96);
#pragma unroll 4
    for (int k = 0; k < 32; ++k) {
        float v = w[(((dy * 3 + dx) * CH) + ci0 + k) * CH + co];
        dst[k * 96 + co] = f2tf32f(v);
    }
}

// ======================= conv via mma.sync TF32 =======================
// Block: 128 threads (4 warps). Tile: full 128-px row x 96 couts.
// Warp: 32 px x 96 couts = 2 mb x 12 nb m16n8k8 fragments, C = 96 regs.
// K loop: 27 chunks of 32 (dy, dx, ci-third), SINGLE-buffered smem
// (2 syncthreads per chunk), register prefetch of chunk c+1.
#define A_STRIDE 36    /* [128 px][36]: frag LDS bank = 4*gid+tig : conflict-free */
#define B_STRIDE 104   /* [32 k][104]: frag LDS bank = 8*tig+gid : conflict-free */

__global__ void __launch_bounds__(128)
conv_mma_kernel(const float* __restrict__ x1, const float* __restrict__ x2,
                const float* __restrict__ x3,
                const float* __restrict__ gq, const float* __restrict__ bq,
                const float* __restrict__ mq, const float* __restrict__ vq,
                const float* __restrict__ gk, const float* __restrict__ bk,
                const float* __restrict__ mk, const float* __restrict__ vk,
                const float* __restrict__ gv, const float* __restrict__ bv,
                const float* __restrict__ mv, const float* __restrict__ vvv)
{
    __shared__ __align__(16) float sA[128 * A_STRIDE];   // 18432 B
    __shared__ __align__(16) float sB[32 * B_STRIDE];    // 13312 B
    __shared__ float s_scale[CH], s_shift[CH];

    const int tid  = threadIdx.x;
    const int conv = blockIdx.y;
    const int tb   = blockIdx.x;            // 0..1023
    const int b    = tb >> 7;               // batch
    const int y    = tb & 127;              // output row

    const float* xin = (conv == 0) ? x1 : (conv == 1) ? x2 : x3;
    float* outp      = (conv == 0) ? g_q : (conv == 1) ? g_k : g_v;

    if (tid < CH) {
        const float* gm = (conv == 0) ? gq : (conv == 1) ? gk : gv;
        const float* bt = (conv == 0) ? bq : (conv == 1) ? bk : bv;
        const float* mu = (conv == 0) ? mq : (conv == 1) ? mk : mv;
        const float* vr = (conv == 0) ? vq : (conv == 1) ? vk : vvv;
        float s = gm[tid] * rsqrtf(vr[tid] + EPS_BN);
        s_scale[tid] = s;
        s_shift[tid] = bt[tid] - mu[tid] * s;
    }

    const int lane = tid & 31;
    const int wp   = tid >> 5;
    const int gid  = lane >> 2;   // 0..7
    const int tig  = lane & 3;    // 0..3

    const size_t imgbase = (size_t)b * (HW * HW * CH);
    const float* Bw = g_Bw + (size_t)conv * 27 * (32 * 96);

    float4 a_pre[8];    // 32 ch of pixel tid
    uint4  b_pre[6];    // weight slice

    auto load_chunk = [&](int c) {
        const int dy  = c / 9;
        const int dxx = (c % 9) / 3;
        const int ci0 = (c % 3) * 32;
        const int gy  = y + dy - 1;
        const int gx  = tid + dxx - 1;
        if ((unsigned)gy < (unsigned)HW && (unsigned)gx < (unsigned)HW) {
            const float4* src = (const float4*)(xin + imgbase +
                                 ((size_t)(gy * HW + gx) * CH + ci0));
#pragma unroll
            for (int j = 0; j < 8; ++j) a_pre[j] = src[j];
        } else {
#pragma unroll
            for (int j = 0; j < 8; ++j) a_pre[j] = make_float4(0.f, 0.f, 0.f, 0.f);
        }
        const uint4* wsrc = (const uint4*)(Bw + (size_t)c * (32 * 96));
#pragma unroll
        for (int i = 0; i < 6; ++i) b_pre[i] = wsrc[tid + i * 128];
    };

    auto store_chunk = [&]() {
        float4* adst = (float4*)(sA + tid * A_STRIDE);
#pragma unroll
        for (int j = 0; j < 8; ++j) {
            float4 v = a_pre[j];
            adst[j] = make_float4(f2tf32f(v.x), f2tf32f(v.y), f2tf32f(v.z), f2tf32f(v.w));
        }
#pragma unroll
        for (int i = 0; i < 6; ++i) {
            int idx = tid + i * 128;        // float4 index over [32][24]
            int k   = idx / 24;
            int c4  = idx % 24;
            *(uint4*)(sB + k * B_STRIDE + c4 * 4) = b_pre[i];
        }
    };

    float4 C[24];       // [mb][nb] : mb*12 + nb
#pragma unroll
    for (int i = 0; i < 24; ++i) C[i] = make_float4(0.f, 0.f, 0.f, 0.f);

    load_chunk(0);
    store_chunk();
    __syncthreads();

    for (int c = 0; c < 27; ++c) {
        if (c < 26) load_chunk(c + 1);

        // warp consumes px [32*wp, 32*wp+32)
        const float* A0 = sA + (wp * 32 + gid) * A_STRIDE + tig;
        const float* B0 = sB + tig * B_STRIDE + gid;
#pragma unroll
        for (int ks = 0; ks < 4; ++ks) {
            uint32_t a[2][4];
#pragma unroll
            for (int mb = 0; mb < 2; ++mb) {
                const float* Am = A0 + mb * 16 * A_STRIDE;
                a[mb][0] = __float_as_uint(Am[ks * 8]);
                a[mb][1] = __float_as_uint(Am[8 * A_STRIDE + ks * 8]);
                a[mb][2] = __float_as_uint(Am[ks * 8 + 4]);
                a[mb][3] = __float_as_uint(Am[8 * A_STRIDE + ks * 8 + 4]);
            }
            const float* Brow = B0 + ks * 8 * B_STRIDE;
#pragma unroll
            for (int nb = 0; nb < 12; ++nb) {
                uint32_t bb[2];
                bb[0] = __float_as_uint(Brow[nb * 8]);
                bb[1] = __float_as_uint(Brow[4 * B_STRIDE + nb * 8]);
                mma_tf32(C[nb],      a[0], bb);
                mma_tf32(C[12 + nb], a[1], bb);
            }
        }
        if (c < 26) {
            __syncthreads();   // all frag reads of chunk c done
            store_chunk();
            __syncthreads();   // chunk c+1 visible
        }
    }

    // ---- epilogue: BN + sigmoid, float2 stores (c0,c1 adjacent cols) ----
#pragma unroll
    for (int mb = 0; mb < 2; ++mb) {
        const int px = wp * 32 + mb * 16 + gid;
        float* orow0 = outp + imgbase + ((size_t)(y * HW) + px) * CH;
        float* orow1 = orow0 + 8 * CH;      // pixel px+8
#pragma unroll
        for (int nb = 0; nb < 12; ++nb) {
            float4 Cc = C[mb * 12 + nb];
            int col = nb * 8 + 2 * tig;
            float sc0 = s_scale[col],     sh0 = s_shift[col];
            float sc1 = s_scale[col + 1], sh1 = s_shift[col + 1];
            float2 r0, r1;
            r0.x = sigmoidf_(Cc.x * sc0 + sh0);
            r0.y = sigmoidf_(Cc.y * sc1 + sh1);
            r1.x = sigmoidf_(Cc.z * sc0 + sh0);
            r1.y = sigmoidf_(Cc.w * sc1 + sh1);
            *(float2*)(orow0 + col) = r0;
            *(float2*)(orow1 + col) = r1;
        }
    }
}

// ======================= attention + final =======================
__global__ __launch_bounds__(256)
void spat_att_kernel()
{
    int p    = blockIdx.x * 8 + (threadIdx.x >> 5);
    int lane = threadIdx.x & 31;
    const float* qp = g_q + (size_t)p * CH;
    const float* kp = g_k + (size_t)p * CH;
    float tpl = 0.f, tpp = 0.f, tll = 0.f;
#pragma unroll
    for (int i = 0; i < 3; ++i) {
        float a = qp[lane + i * 32];
        float b = kp[lane + i * 32];
        tpl += a * b; tpp += a * a; tll += b * b;
    }
#pragma unroll
    for (int off = 16; off; off >>= 1) {
        tpl += __shfl_xor_sync(0xffffffffu, tpl, off);
        tpp += __shfl_xor_sync(0xffffffffu, tpp, off);
        tll += __shfl_xor_sync(0xffffffffu, tll, off);
    }
    if (lane == 0) g_att_spat[p] = ftanimoto(tpl, tpp, tll);
}

// stage 1: 1024 blocks (b, 128-pixel slice), 192 threads (96 c x 2 halves)
__global__ __launch_bounds__(192)
void chan_part_kernel()
{
    __shared__ float sp[2][96][3];
    const int t    = threadIdx.x;
    const int c    = t % 96;
    const int half = t / 96;
    const int blk  = blockIdx.x;         // 0..1023
    const int b    = blk >> 7;
    const int sl   = blk & 127;
    const size_t pixbase = (size_t)b * 16384 + sl * 128 + half * 64;
    const float* qb = g_q + pixbase * CH + c;
    const float* kb = g_k + pixbase * CH + c;
    float tpl = 0.f, tpp = 0.f, tll = 0.f;
#pragma unroll 4
    for (int i = 0; i < 64; ++i) {
        size_t off = (size_t)i * CH;
        float a = qb[off];
        float bb = kb[off];
        tpl += a * bb; tpp += a * a; tll += bb * bb;
    }
    sp[half][c][0] = tpl; sp[half][c][1] = tpp; sp[half][c][2] = tll;
    __syncthreads();
    if (t < 96) {
        float* o = g_part + blk * 288 + t * 3;
        o[0] = sp[0][t][0] + sp[1][t][0];
        o[1] = sp[0][t][1] + sp[1][t][1];
        o[2] = sp[0][t][2] + sp[1][t][2];
    }
}

// stage 2: reduce 128 slices per (b,c)
__global__ void chan_att_kernel()
{
    int b = blockIdx.x;
    int c = threadIdx.x;    // 96 threads
    float tpl = 0.f, tpp = 0.f, tll = 0.f;
    for (int i = 0; i < 128; ++i) {
        const float* pp = g_part + ((size_t)(b * 128 + i)) * 288 + c * 3;
        tpl += pp[0]; tpp += pp[1]; tll += pp[2];
    }
    g_att_chan[b * CH + c] = ftanimoto(tpl, tpp, tll);
}

__global__ __launch_bounds__(256)
void final_kernel(const float* __restrict__ gn, const float* __restrict__ bnb,
                  const float* __restrict__ mn, const float* __restrict__ vn,
                  float* __restrict__ out)
{
    int i4   = blockIdx.x * 256 + threadIdx.x;
    int flat = i4 * 4;
    int pix  = flat / CH;
    int c    = flat % CH;
    int b    = pix >> 14;

    float4 v4 = *(const float4*)(g_v + (size_t)flat);
    float  as = g_att_spat[pix];
    float4 ac = *(const float4*)(g_att_chan + b * CH + c);
    float4 gg = *(const float4*)(gn  + c);
    float4 bb = *(const float4*)(bnb + c);
    float4 mm = *(const float4*)(mn  + c);
    float4 vv = *(const float4*)(vn  + c);

    float4 r;
    float s;
    s = gg.x * rsqrtf(vv.x + EPS_BN); r.x = (0.5f * v4.x * (ac.x + as) - mm.x) * s + bb.x;
    s = gg.y * rsqrtf(vv.y + EPS_BN); r.y = (0.5f * v4.y * (ac.y + as) - mm.y) * s + bb.y;
    s = gg.z * rsqrtf(vv.z + EPS_BN); r.z = (0.5f * v4.z * (ac.z + as) - mm.z) * s + bb.z;
    s = gg.w * rsqrtf(vv.w + EPS_BN); r.w = (0.5f * v4.w * (ac.w + as) - mm.w) * s + bb.w;
    *(float4*)(out + (size_t)flat) = r;
}

// ======================= launch =======================
extern "C" void kernel_launch(void* const* d_in, const int* in_sizes, int n_in,
                              void* d_out, int out_size)
{
    const float* x1 = (const float*)d_in[0];
    const float* x2 = (const float*)d_in[1];
    const float* x3 = (const float*)d_in[2];
    const float* wq = (const float*)d_in[3];
    const float* gq = (const float*)d_in[4];
    const float* bq = (const float*)d_in[5];
    const float* mq = (const float*)d_in[6];
    const float* vq = (const float*)d_in[7];
    const float* wk = (const float*)d_in[8];
    const float* gk = (const float*)d_in[9];
    const float* bk = (const float*)d_in[10];
    const float* mk = (const float*)d_in[11];
    const float* vk = (const float*)d_in[12];
    const float* wv = (const float*)d_in[13];
    const float* gv = (const float*)d_in[14];
    const float* bv = (const float*)d_in[15];
    const float* mv = (const float*)d_in[16];
    const float* vv = (const float*)d_in[17];
    const float* gn  = (const float*)d_in[18];
    const float* bnb = (const float*)d_in[19];
    const float* mn  = (const float*)d_in[20];
    const float* vn  = (const float*)d_in[21];

    prep_weights<<<81, 96>>>(wq, wk, wv);

    dim3 cgrid(1024, 3);   // (128 rows * 8 batches) x 3 convs, full-row tiles
    conv_mma_kernel<<<cgrid, 128>>>(x1, x2, x3,
                                    gq, bq, mq, vq,
                                    gk, bk, mk, vk,
                                    gv, bv, mv, vv);

    spat_att_kernel<<<NPIX / 8, 256>>>();
    chan_part_kernel<<<1024, 192>>>();
    chan_att_kernel<<<NB, 96>>>();
    final_kernel<<<(NPIX * CH / 4) / 256, 256>>>(gn, bnb, mn, vn, (float*)d_out);
}